// round 3
// baseline (speedup 1.0000x reference)
#include <cuda_runtime.h>
#include <math.h>

typedef unsigned long long ull;

#define DIMK 256
#define SEQL 2048
#define NTOK 2049
#define BATCH 2
#define WINW 64
#define KNB 129          // 2*WIN+1
#define HEADS 4
#define RANK 32
#define HR 128           // HEADS*RANK
#define NLAYERS 3
#define EPSV 1e-6f
#define ROWS (BATCH*NTOK) // 4098
#define HID 512

// ---------------- scratch (device globals; no runtime allocation) -------------
__device__ float g_val [ROWS*DIMK];
__device__ float g_val2[ROWS*DIMK];
__device__ float g_state [ROWS];
__device__ float g_state2[ROWS];
__device__ float g_q[ROWS*HR];
__device__ float g_k[ROWS*HR];
__device__ float g_h[ROWS*HID];

__device__ __forceinline__ float sgnf(float x){ return (float)((x>0.f)-(x<0.f)); }
__device__ __forceinline__ float geluf(float x){ return 0.5f*x*(1.f+erff(x*0.70710678118654752440f)); }

// packed fp32x2 FMA (FFMA2) — 2 fp32 FMA per instruction, rt=2/SMSP
__device__ __forceinline__ void fma2(ull& acc, ull a, ull b){
    asm("fma.rn.f32x2 %0, %1, %2, %0;" : "+l"(acc) : "l"(a), "l"(b));
}
__device__ __forceinline__ ull add2(ull a, ull b){
    ull r; asm("add.rn.f32x2 %0, %1, %2;" : "=l"(r) : "l"(a), "l"(b)); return r;
}
__device__ __forceinline__ float2 upk(ull v){
    float2 f; asm("mov.b64 {%0,%1}, %2;" : "=f"(f.x), "=f"(f.y) : "l"(v)); return f;
}

// ---------------- embed: tok = emb[id]+pos; val=unit(tok); tstate=tok.Ws+bs ----
__global__ void k_embed(const int* __restrict__ ids, const float* __restrict__ emb,
                        const float* __restrict__ pos, const float* __restrict__ av,
                        const float* __restrict__ as,  const float* __restrict__ Ws,
                        const float* __restrict__ bs){
    __shared__ float s1[8], s2m[8];
    int bi = blockIdx.x / NTOK, n = blockIdx.x % NTOK, d = threadIdx.x;
    float t, traw = 0.f;
    if (n == 0) { t = av[d]; }
    else { int s = n-1; int id = ids[bi*SEQL+s]; t = emb[id*DIMK+d] + pos[s*DIMK+d]; traw = t; }
    float a = t*t, b = traw*Ws[d];
    int lane = d & 31, w = d >> 5;
    #pragma unroll
    for (int o=16;o;o>>=1){ a += __shfl_xor_sync(~0u,a,o); b += __shfl_xor_sync(~0u,b,o); }
    if (lane==0){ s1[w]=a; s2m[w]=b; }
    __syncthreads();
    if (w==0){
        float x = (lane<8)? s1[lane]:0.f, y = (lane<8)? s2m[lane]:0.f;
        #pragma unroll
        for (int o=4;o;o>>=1){ x += __shfl_xor_sync(~0u,x,o); y += __shfl_xor_sync(~0u,y,o); }
        if (lane==0){ s1[0]=x; s2m[0]=y; }
    }
    __syncthreads();
    float norm = sqrtf(s1[0]);
    g_val[(bi*NTOK+n)*DIMK + d] = t / fmaxf(norm, EPSV);
    if (d==0) g_state[bi*NTOK+n] = (n==0) ? as[0] : (s2m[0] + bs[0]);
}

// ---------------- q/k projection: 16-row tiles, f32x2 -------------------------
__global__ void k_qk(const float* __restrict__ U, const float* __restrict__ V, int layer){
    __shared__ __align__(16) float2 sA2[16*DIMK];  // dup activations, 32KB
    int row0 = blockIdx.x*16;
    for (int e=threadIdx.x; e<16*DIMK; e+=256){
        int row = row0 + (e>>8);
        float v = (row<ROWS) ? g_val[row*DIMK + (e&255)] : 0.f;
        sA2[e] = make_float2(v,v);
    }
    __syncthreads();
    int cg = threadIdx.x & 63;   // col quad: cols 4cg..4cg+3 of 256 (q|k)
    int rh = threadIdx.x >> 6;   // row group: rows rh*4..rh*4+3
    int col = cg*4;
    const float* W; float* out; int ocol;
    if (col < HR){ W = U + layer*DIMK*HR + col;      out = g_q; ocol = col; }
    else         { W = V + layer*DIMK*HR + (col-HR); out = g_k; ocol = col-HR; }
    ull acc[4][2] = {};
    for (int d=0; d<DIMK; d+=2){
        ulonglong2 w0 = *(const ulonglong2*)&W[(d+0)*HR];
        ulonglong2 w1 = *(const ulonglong2*)&W[(d+1)*HR];
        #pragma unroll
        for (int r=0;r<4;r++){
            ulonglong2 a = *(const ulonglong2*)&sA2[(rh*4+r)*DIMK + d];
            fma2(acc[r][0], a.x, w0.x); fma2(acc[r][1], a.x, w0.y);
            fma2(acc[r][0], a.y, w1.x); fma2(acc[r][1], a.y, w1.y);
        }
    }
    #pragma unroll
    for (int r=0;r<4;r++){
        int row = row0 + rh*4 + r;
        if (row<ROWS){
            float2 a0 = upk(acc[r][0]), a1 = upk(acc[r][1]);
            *(float4*)&out[row*HR + ocol] = make_float4(a0.x, a0.y, a1.x, a1.y);
        }
    }
}

// ---------------- fused windowed attention, 8 tokens per block, f32x2 ---------
#define SKP 136   // padded K row (2-way instead of 4-way LDS.128 conflicts)
#define ATTN_SMEM_FLOATS (144*SKP + 8*HR + 8*132 + 144 + 8 + 8 + 8*132*2)

__global__ void k_attn(){
    extern __shared__ __align__(16) float sm[];
    float*    sK   = sm;                    // [144][136] padded keys
    float*    sQ   = sK + 144*SKP;          // [8][128]
    float*    sS   = sQ + 8*HR;             // [8][132] raw scores
    float*    sSt  = sS + 8*132;            // [144] neighbor states
    float*    sSum = sSt + 144;             // [8] norm^2
    unsigned* sMax = (unsigned*)(sSum + 8); // [8] max|dval|
    float2*   sSd  = (float2*)(sMax + 8);   // [8][132] dup weights
    int bi = blockIdx.y;
    int t0 = blockIdx.x*8;
    int tid = threadIdx.x;
    int lane = tid & 31;
    int nvalid = min(8, NTOK - t0);
    int base = t0 - WINW;

    const float* kb = g_k + bi*NTOK*HR;
    for (int e=tid; e<144*HR; e+=256){
        int r = e>>7;
        int cl = min(max(base+r,0), NTOK-1);
        sK[r*SKP + (e&127)] = kb[cl*HR + (e&127)];
    }
    const float* qb = g_q + bi*NTOK*HR;
    for (int e=tid; e<8*HR; e+=256){
        int n = t0 + (e>>7);
        sQ[e] = (n<NTOK) ? qb[n*HR + (e&127)] : 0.f;
    }
    for (int r=tid; r<144; r+=256){
        int cl = min(max(base+r,0), NTOK-1);
        sSt[r] = g_state[bi*NTOK + cl];
    }
    if (tid<8){ sSum[tid]=0.f; sMax[tid]=0u; }
    __syncthreads();

    // scores: s[i][jo] = max_h (q_i . k_{i+jo}) / sqrt(R), f32x2 over rank
    for (int p=tid; p<nvalid*KNB; p+=256){
        int i = p/KNB, jo = p - i*KNB;
        const float* qq = sQ + i*HR;
        const float* kk = sK + (i+jo)*SKP;
        float best = -INFINITY;
        #pragma unroll
        for (int h=0; h<HEADS; h++){
            ull acc = 0ull;
            #pragma unroll
            for (int r4=0; r4<RANK; r4+=4){
                ulonglong2 qv = *(const ulonglong2*)&qq[h*RANK+r4];
                ulonglong2 kv = *(const ulonglong2*)&kk[h*RANK+r4];
                fma2(acc, qv.x, kv.x);
                fma2(acc, qv.y, kv.y);
            }
            float2 f = upk(acc);
            best = fmaxf(best, f.x + f.y);
        }
        sS[i*132+jo] = best * 0.17677669529663687f;  // 1/sqrt(32)
    }
    __syncthreads();

    // per-token signed softmax (warp w owns token t0+w) + dstate
    int w = tid>>5;
    if (w < nvalid){
        int n = t0 + w;
        float m = -INFINITY;
        for (int jo=lane; jo<KNB; jo+=32){
            int ab = n - WINW + jo;
            float s = sS[w*132+jo];
            float a = (ab>=0 && ab<NTOK) ? fabsf(s) : -INFINITY;
            m = fmaxf(m, a);
        }
        #pragma unroll
        for (int o=16;o;o>>=1) m = fmaxf(m, __shfl_xor_sync(~0u,m,o));
        float sum = 0.f, wv[5];
        int c = 0;
        for (int jo=lane; jo<KNB; jo+=32, c++){
            int ab = n - WINW + jo;
            bool v = (ab>=0 && ab<NTOK);
            float s = sS[w*132+jo];
            float e = v ? expf(fabsf(s)-m) : 0.f;
            sum += e;
            wv[c] = v ? sgnf(s)*e : 0.f;
        }
        #pragma unroll
        for (int o=16;o;o>>=1) sum += __shfl_xor_sync(~0u,sum,o);
        float inv = 1.f/sum, ds = 0.f;
        c = 0;
        for (int jo=lane; jo<KNB; jo+=32, c++){
            float wg = wv[c]*inv;
            sSd[w*132+jo] = make_float2(wg, wg);
            ds += wg * sSt[w+jo];
        }
        #pragma unroll
        for (int o=16;o;o>>=1) ds += __shfl_xor_sync(~0u,ds,o);
        if (lane==0) g_state2[bi*NTOK+n] = g_state[bi*NTOK+n] + ds;
    }
    __syncthreads();

    // dval: thread owns col pair (2*d2, 2*d2+1) for 4 tokens, f32x2
    int d2 = tid & 127;
    int hh = tid >> 7;               // token half: tokens hh*4..hh*4+3
    ull acc[4] = {0,0,0,0};
    const float* vb = g_val + bi*NTOK*DIMK;
    int rmax = nvalid - 1 + 2*WINW;
    for (int r=0; r<=rmax; r++){
        int cl = min(max(base+r,0), NTOK-1);
        ull v2 = *(const ull*)&vb[cl*DIMK + 2*d2];
        #pragma unroll
        for (int ii=0; ii<4; ii++){
            int jo = r - (hh*4+ii);
            if (jo>=0 && jo<KNB){
                ull wd = *(const ull*)&sSd[(hh*4+ii)*132 + jo];
                fma2(acc[ii], wd, v2);
            }
        }
    }

    // epilogue: updated = val + dval; conditional unit-norm (touched)
    float2 u[4];
    #pragma unroll
    for (int ii=0; ii<4; ii++){
        int i = hh*4+ii, n = t0+i;
        if (n < NTOK){
            ull vres = *(const ull*)&vb[n*DIMK + 2*d2];
            ull up = add2(vres, acc[ii]);
            u[ii] = upk(up);
            float2 a = upk(acc[ii]);
            float s2 = u[ii].x*u[ii].x + u[ii].y*u[ii].y;
            float am = fmaxf(fabsf(a.x), fabsf(a.y));
            #pragma unroll
            for (int o=16;o;o>>=1){ s2 += __shfl_xor_sync(~0u,s2,o); am = fmaxf(am, __shfl_xor_sync(~0u,am,o)); }
            if (lane==0){ atomicAdd(&sSum[i], s2); atomicMax(&sMax[i], __float_as_uint(am)); }
        }
    }
    __syncthreads();
    float* v2o = g_val2 + bi*NTOK*DIMK;
    #pragma unroll
    for (int ii=0; ii<4; ii++){
        int i = hh*4+ii, n = t0+i;
        if (n < NTOK){
            bool touched = __uint_as_float(sMax[i]) > 0.f;
            float inv = touched ? 1.f/fmaxf(sqrtf(sSum[i]), EPSV) : 1.f;
            *(float2*)&v2o[n*DIMK + 2*d2] = make_float2(u[ii].x*inv, u[ii].y*inv);
        }
    }
}

// ---------------- batch-global signed softmax over state ----------------------
__global__ void k_state_sm(float* __restrict__ out, int last){
    __shared__ float sred[32];
    int bi = blockIdx.x, tid = threadIdx.x, lane = tid&31, w = tid>>5;
    const float* in = g_state2 + bi*NTOK;
    float* dst = last ? out : g_state;
    int n0 = tid, n1 = tid+1024, n2 = tid+2048;
    float v0=0.f, v1=0.f, v2=0.f;
    float m = -INFINITY;
    if (n0<NTOK){ v0=in[n0]; m=fmaxf(m,fabsf(v0)); }
    if (n1<NTOK){ v1=in[n1]; m=fmaxf(m,fabsf(v1)); }
    if (n2<NTOK){ v2=in[n2]; m=fmaxf(m,fabsf(v2)); }
    #pragma unroll
    for (int o=16;o;o>>=1) m = fmaxf(m, __shfl_xor_sync(~0u,m,o));
    if (lane==0) sred[w] = m;
    __syncthreads();
    if (w==0){ float x = sred[lane];
        #pragma unroll
        for (int o=16;o;o>>=1) x = fmaxf(x, __shfl_xor_sync(~0u,x,o));
        if (lane==0) sred[0]=x; }
    __syncthreads();
    float mm = sred[0];
    __syncthreads();
    float e0=0.f, e1=0.f, e2=0.f, sum=0.f;
    if (n0<NTOK){ e0=expf(fabsf(v0)-mm); sum+=e0; }
    if (n1<NTOK){ e1=expf(fabsf(v1)-mm); sum+=e1; }
    if (n2<NTOK){ e2=expf(fabsf(v2)-mm); sum+=e2; }
    #pragma unroll
    for (int o=16;o;o>>=1) sum += __shfl_xor_sync(~0u,sum,o);
    if (lane==0) sred[w] = sum;
    __syncthreads();
    if (w==0){ float x = sred[lane];
        #pragma unroll
        for (int o=16;o;o>>=1) x += __shfl_xor_sync(~0u,x,o);
        if (lane==0) sred[0]=x; }
    __syncthreads();
    float inv = 1.f/sred[0];
    if (n0<NTOK) dst[bi*NTOK+n0] = sgnf(v0)*e0*inv;
    if (n1<NTOK) dst[bi*NTOK+n1] = sgnf(v1)*e1*inv;
    if (n2<NTOK) dst[bi*NTOK+n2] = sgnf(v2)*e2*inv;
}

// ---------------- MLP fc1 + gelu: (rows,256)->(rows,512), f32x2 ---------------
__global__ void k_mlp1(const float* __restrict__ W1, const float* __restrict__ b1, int layer){
    __shared__ __align__(16) float2 sA2[16*DIMK];  // 32KB dup activations
    int row0 = blockIdx.x*16;
    for (int e=threadIdx.x; e<16*DIMK; e+=256){
        int row = row0 + (e>>8);
        float v = (row<ROWS) ? g_val2[row*DIMK + (e&255)] : 0.f;
        sA2[e] = make_float2(v,v);
    }
    __syncthreads();
    int cg = threadIdx.x & 127;   // cols 4cg..4cg+3 of 512
    int rh = threadIdx.x >> 7;    // rows rh*8..rh*8+7
    int col = cg*4;
    const float* W = W1 + layer*DIMK*HID + col;
    ull acc[8][2] = {};
    for (int d=0; d<DIMK; d+=2){
        ulonglong2 w0 = *(const ulonglong2*)&W[(d+0)*HID];
        ulonglong2 w1 = *(const ulonglong2*)&W[(d+1)*HID];
        #pragma unroll
        for (int r=0;r<8;r++){
            ulonglong2 a = *(const ulonglong2*)&sA2[(rh*8+r)*DIMK + d];
            fma2(acc[r][0], a.x, w0.x); fma2(acc[r][1], a.x, w0.y);
            fma2(acc[r][0], a.y, w1.x); fma2(acc[r][1], a.y, w1.y);
        }
    }
    float4 bv = *(const float4*)&b1[layer*HID + col];
    #pragma unroll
    for (int r=0;r<8;r++){
        int row = row0 + rh*8 + r;
        if (row<ROWS){
            float2 a0 = upk(acc[r][0]), a1 = upk(acc[r][1]);
            *(float4*)&g_h[row*HID + col] =
                make_float4(geluf(a0.x+bv.x), geluf(a0.y+bv.y), geluf(a1.x+bv.z), geluf(a1.y+bv.w));
        }
    }
}

// ---------------- MLP fc2 + residual + unit-norm, f32x2 -----------------------
__global__ void k_mlp2(const float* __restrict__ W2, const float* __restrict__ b2,
                       int layer, float* __restrict__ out, int last){
    extern __shared__ __align__(16) float2 sH2[];  // [16*512] dup, 64KB
    __shared__ float sSum[16];
    int row0 = blockIdx.x*16;
    for (int e=threadIdx.x; e<16*HID; e+=256){
        int row = row0 + (e>>9);
        float v = (row<ROWS) ? g_h[row*HID + (e&511)] : 0.f;
        sH2[e] = make_float2(v,v);
    }
    if (threadIdx.x<16) sSum[threadIdx.x] = 0.f;
    __syncthreads();
    int cg = threadIdx.x & 63;    // cols 4cg..4cg+3 of 256
    int rh = threadIdx.x >> 6;    // rows rh*4..rh*4+3
    int col = cg*4;
    const float* W = W2 + layer*HID*DIMK + col;
    ull acc[4][2] = {};
    for (int d=0; d<HID; d+=2){
        ulonglong2 w0 = *(const ulonglong2*)&W[(d+0)*DIMK];
        ulonglong2 w1 = *(const ulonglong2*)&W[(d+1)*DIMK];
        #pragma unroll
        for (int r=0;r<4;r++){
            ulonglong2 a = *(const ulonglong2*)&sH2[(rh*4+r)*HID + d];
            fma2(acc[r][0], a.x, w0.x); fma2(acc[r][1], a.x, w0.y);
            fma2(acc[r][0], a.y, w1.x); fma2(acc[r][1], a.y, w1.y);
        }
    }
    float4 bv = *(const float4*)&b2[layer*DIMK + col];
    int lane = threadIdx.x & 31;
    float4 u[4];
    #pragma unroll
    for (int r=0;r<4;r++){
        int row = row0 + rh*4 + r;
        if (row<ROWS){
            float4 res = *(const float4*)&g_val2[row*DIMK + col];
            float2 a0 = upk(acc[r][0]), a1 = upk(acc[r][1]);
            u[r] = make_float4(res.x+a0.x+bv.x, res.y+a0.y+bv.y, res.z+a1.x+bv.z, res.w+a1.y+bv.w);
            float s2 = u[r].x*u[r].x + u[r].y*u[r].y + u[r].z*u[r].z + u[r].w*u[r].w;
            #pragma unroll
            for (int o=16;o;o>>=1) s2 += __shfl_xor_sync(~0u,s2,o);
            if (lane==0) atomicAdd(&sSum[rh*4+r], s2);
        }
    }
    __syncthreads();
    #pragma unroll
    for (int r=0;r<4;r++){
        int row = row0 + rh*4 + r;
        if (row<ROWS){
            float inv = 1.f/fmaxf(sqrtf(sSum[rh*4+r]), EPSV);
            if (last){
                // out+ROWS is only 8B-aligned (4098 floats) -> use float2 stores
                float* dst = out + row*DIMK + col;
                *(float2*)&dst[0] = make_float2(u[r].x*inv, u[r].y*inv);
                *(float2*)&dst[2] = make_float2(u[r].z*inv, u[r].w*inv);
            } else {
                *(float4*)&g_val[row*DIMK + col] =
                    make_float4(u[r].x*inv, u[r].y*inv, u[r].z*inv, u[r].w*inv);
            }
        }
    }
}

extern "C" void kernel_launch(void* const* d_in, const int* in_sizes, int n_in,
                              void* d_out, int out_size){
    const int*   ids = (const int*)  d_in[0];
    const float* emb = (const float*)d_in[1];
    const float* pos = (const float*)d_in[2];
    const float* av  = (const float*)d_in[3];
    const float* as  = (const float*)d_in[4];
    const float* Ws  = (const float*)d_in[5];
    const float* bs  = (const float*)d_in[6];
    const float* U   = (const float*)d_in[7];
    const float* V   = (const float*)d_in[8];
    const float* W1  = (const float*)d_in[9];
    const float* b1  = (const float*)d_in[10];
    const float* W2  = (const float*)d_in[11];
    const float* b2  = (const float*)d_in[12];
    float* out = (float*)d_out;

    size_t attn_smem = ATTN_SMEM_FLOATS * sizeof(float);
    size_t mlp2_smem = 16*HID*sizeof(float2);
    cudaFuncSetAttribute(k_attn, cudaFuncAttributeMaxDynamicSharedMemorySize, (int)attn_smem);
    cudaFuncSetAttribute(k_mlp2, cudaFuncAttributeMaxDynamicSharedMemorySize, (int)mlp2_smem);

    k_embed<<<ROWS, 256>>>(ids, emb, pos, av, as, Ws, bs);
    int rb = (ROWS + 15)/16;
    dim3 ga((NTOK + 7)/8, BATCH);
    for (int l=0; l<NLAYERS; l++){
        int last = (l == NLAYERS-1);
        k_qk  <<<rb, 256>>>(U, V, l);
        k_attn<<<ga, 256, attn_smem>>>();
        k_state_sm<<<BATCH, 1024>>>(out, last);
        k_mlp1<<<rb, 256>>>(W1, b1, l);
        k_mlp2<<<rb, 256, mlp2_smem>>>(W2, b2, l, out + ROWS, last);
    }
}

// round 4
// speedup vs baseline: 1.0320x; 1.0320x over previous
#include <cuda_runtime.h>
#include <math.h>

typedef unsigned long long ull;

#define DIMK 256
#define SEQL 2048
#define NTOK 2049
#define BATCH 2
#define WINW 64
#define KNB 129          // 2*WIN+1
#define HEADS 4
#define RANK 32
#define HR 128           // HEADS*RANK
#define NLAYERS 3
#define EPSV 1e-6f
#define ROWS (BATCH*NTOK) // 4098
#define HID 512

// ---------------- scratch (device globals; no runtime allocation) -------------
__device__ float g_val [ROWS*DIMK];
__device__ float g_val2[ROWS*DIMK];
__device__ float g_state [ROWS];
__device__ float g_state2[ROWS];
__device__ float g_q[ROWS*HR];
__device__ float g_k[ROWS*HR];
__device__ float g_h[ROWS*HID];

__device__ __forceinline__ float sgnf(float x){ return (float)((x>0.f)-(x<0.f)); }
__device__ __forceinline__ float geluf(float x){ return 0.5f*x*(1.f+erff(x*0.70710678118654752440f)); }

// packed fp32x2 FMA (FFMA2) — 2 fp32 FMA per instruction, rt=2/SMSP
__device__ __forceinline__ void fma2(ull& acc, ull a, ull b){
    asm("fma.rn.f32x2 %0, %1, %2, %0;" : "+l"(acc) : "l"(a), "l"(b));
}
__device__ __forceinline__ ull add2(ull a, ull b){
    ull r; asm("add.rn.f32x2 %0, %1, %2;" : "=l"(r) : "l"(a), "l"(b)); return r;
}
__device__ __forceinline__ float2 upk(ull v){
    float2 f; asm("mov.b64 {%0,%1}, %2;" : "=f"(f.x), "=f"(f.y) : "l"(v)); return f;
}
// duplicate a scalar into a packed f32x2 operand (1 MOV, fits in spare issue slots)
__device__ __forceinline__ ull dup(float x){
    ull r; asm("mov.b64 %0, {%1,%1};" : "=l"(r) : "f"(x)); return r;
}

// ---------------- embed: tok = emb[id]+pos; val=unit(tok); tstate=tok.Ws+bs ----
__global__ void k_embed(const int* __restrict__ ids, const float* __restrict__ emb,
                        const float* __restrict__ pos, const float* __restrict__ av,
                        const float* __restrict__ as,  const float* __restrict__ Ws,
                        const float* __restrict__ bs){
    __shared__ float s1[8], s2m[8];
    int bi = blockIdx.x / NTOK, n = blockIdx.x % NTOK, d = threadIdx.x;
    float t, traw = 0.f;
    if (n == 0) { t = av[d]; }
    else { int s = n-1; int id = ids[bi*SEQL+s]; t = emb[id*DIMK+d] + pos[s*DIMK+d]; traw = t; }
    float a = t*t, b = traw*Ws[d];
    int lane = d & 31, w = d >> 5;
    #pragma unroll
    for (int o=16;o;o>>=1){ a += __shfl_xor_sync(~0u,a,o); b += __shfl_xor_sync(~0u,b,o); }
    if (lane==0){ s1[w]=a; s2m[w]=b; }
    __syncthreads();
    if (w==0){
        float x = (lane<8)? s1[lane]:0.f, y = (lane<8)? s2m[lane]:0.f;
        #pragma unroll
        for (int o=4;o;o>>=1){ x += __shfl_xor_sync(~0u,x,o); y += __shfl_xor_sync(~0u,y,o); }
        if (lane==0){ s1[0]=x; s2m[0]=y; }
    }
    __syncthreads();
    float norm = sqrtf(s1[0]);
    g_val[(bi*NTOK+n)*DIMK + d] = t / fmaxf(norm, EPSV);
    if (d==0) g_state[bi*NTOK+n] = (n==0) ? as[0] : (s2m[0] + bs[0]);
}

// ---------------- q/k projection: 16-row tiles, non-dup smem, f32x2 -----------
__global__ void __launch_bounds__(256) k_qk(const float* __restrict__ U,
                                            const float* __restrict__ V, int layer){
    __shared__ __align__(16) float sA[16*DIMK];  // 16KB
    int row0 = blockIdx.x*16;
    for (int e=threadIdx.x; e<16*DIMK; e+=256){
        int row = row0 + (e>>8);
        sA[e] = (row<ROWS) ? g_val[row*DIMK + (e&255)] : 0.f;
    }
    __syncthreads();
    int cq = threadIdx.x & 63;   // col quad: cols 4cq..4cq+3 of 256 (q|k)
    int rg = threadIdx.x >> 6;   // rows rg*4..rg*4+3
    int col = cq*4;
    const float* W; float* out; int ocol;
    if (col < HR){ W = U + layer*DIMK*HR + col;      out = g_q; ocol = col; }
    else         { W = V + layer*DIMK*HR + (col-HR); out = g_k; ocol = col-HR; }
    ull acc[4][2] = {};
    for (int d=0; d<DIMK; d+=2){
        ulonglong2 w0 = *(const ulonglong2*)&W[(d+0)*HR];
        ulonglong2 w1 = *(const ulonglong2*)&W[(d+1)*HR];
        #pragma unroll
        for (int r=0;r<4;r++){
            float2 a = *(const float2*)&sA[(rg*4+r)*DIMK + d];
            ull ax = dup(a.x), ay = dup(a.y);
            fma2(acc[r][0], ax, w0.x); fma2(acc[r][1], ax, w0.y);
            fma2(acc[r][0], ay, w1.x); fma2(acc[r][1], ay, w1.y);
        }
    }
    #pragma unroll
    for (int r=0;r<4;r++){
        int row = row0 + rg*4 + r;
        if (row<ROWS){
            float2 a0 = upk(acc[r][0]), a1 = upk(acc[r][1]);
            *(float4*)&out[row*HR + ocol] = make_float4(a0.x, a0.y, a1.x, a1.y);
        }
    }
}

// ---------------- fused windowed attention, 8 tokens per block, f32x2 ---------
#define SKP 132   // conflict-free for LDS.128 8-thread phases (132 mod 32 = 4)
#define ATTN_SMEM_FLOATS (144*SKP + 8*HR + 8*132 + 144 + 8 + 8 + 8*132*2)

__global__ void k_attn(){
    extern __shared__ __align__(16) float sm[];
    float*    sK   = sm;                    // [144][132] padded keys
    float*    sQ   = sK + 144*SKP;          // [8][128]
    float*    sS   = sQ + 8*HR;             // [8][132] raw scores
    float*    sSt  = sS + 8*132;            // [144] neighbor states
    float*    sSum = sSt + 144;             // [8] norm^2
    unsigned* sMax = (unsigned*)(sSum + 8); // [8] max|dval|
    float2*   sSd  = (float2*)(sMax + 8);   // [8][132] dup weights
    int bi = blockIdx.y;
    int t0 = blockIdx.x*8;
    int tid = threadIdx.x;
    int lane = tid & 31;
    int nvalid = min(8, NTOK - t0);
    int base = t0 - WINW;

    const float* kb = g_k + bi*NTOK*HR;
    for (int e=tid; e<144*HR; e+=256){
        int r = e>>7;
        int cl = min(max(base+r,0), NTOK-1);
        sK[r*SKP + (e&127)] = kb[cl*HR + (e&127)];
    }
    const float* qb = g_q + bi*NTOK*HR;
    for (int e=tid; e<8*HR; e+=256){
        int n = t0 + (e>>7);
        sQ[e] = (n<NTOK) ? qb[n*HR + (e&127)] : 0.f;
    }
    for (int r=tid; r<144; r+=256){
        int cl = min(max(base+r,0), NTOK-1);
        sSt[r] = g_state[bi*NTOK + cl];
    }
    if (tid<8){ sSum[tid]=0.f; sMax[tid]=0u; }
    __syncthreads();

    // scores: s[i][jo] = max_h (q_i . k_{i+jo}) / sqrt(R), f32x2 over rank
    for (int p=tid; p<nvalid*KNB; p+=256){
        int i = p/KNB, jo = p - i*KNB;
        const float* qq = sQ + i*HR;
        const float* kk = sK + (i+jo)*SKP;
        float best = -INFINITY;
        #pragma unroll
        for (int h=0; h<HEADS; h++){
            ull acc = 0ull;
            #pragma unroll
            for (int r4=0; r4<RANK; r4+=4){
                ulonglong2 qv = *(const ulonglong2*)&qq[h*RANK+r4];
                ulonglong2 kv = *(const ulonglong2*)&kk[h*RANK+r4];
                fma2(acc, qv.x, kv.x);
                fma2(acc, qv.y, kv.y);
            }
            float2 f = upk(acc);
            best = fmaxf(best, f.x + f.y);
        }
        sS[i*132+jo] = best * 0.17677669529663687f;  // 1/sqrt(32)
    }
    __syncthreads();

    // per-token signed softmax (warp w owns token t0+w) + dstate
    int w = tid>>5;
    if (w < nvalid){
        int n = t0 + w;
        float m = -INFINITY;
        for (int jo=lane; jo<KNB; jo+=32){
            int ab = n - WINW + jo;
            float s = sS[w*132+jo];
            float a = (ab>=0 && ab<NTOK) ? fabsf(s) : -INFINITY;
            m = fmaxf(m, a);
        }
        #pragma unroll
        for (int o=16;o;o>>=1) m = fmaxf(m, __shfl_xor_sync(~0u,m,o));
        float sum = 0.f, wv[5];
        int c = 0;
        for (int jo=lane; jo<KNB; jo+=32, c++){
            int ab = n - WINW + jo;
            bool v = (ab>=0 && ab<NTOK);
            float s = sS[w*132+jo];
            float e = v ? expf(fabsf(s)-m) : 0.f;
            sum += e;
            wv[c] = v ? sgnf(s)*e : 0.f;
        }
        #pragma unroll
        for (int o=16;o;o>>=1) sum += __shfl_xor_sync(~0u,sum,o);
        float inv = 1.f/sum, ds = 0.f;
        c = 0;
        for (int jo=lane; jo<KNB; jo+=32, c++){
            float wg = wv[c]*inv;
            sSd[w*132+jo] = make_float2(wg, wg);
            ds += wg * sSt[w+jo];
        }
        #pragma unroll
        for (int o=16;o;o>>=1) ds += __shfl_xor_sync(~0u,ds,o);
        if (lane==0) g_state2[bi*NTOK+n] = g_state[bi*NTOK+n] + ds;
    }
    __syncthreads();

    // dval: thread owns col pair (2*d2, 2*d2+1) for 4 tokens, f32x2
    int d2 = tid & 127;
    int hh = tid >> 7;               // token half: tokens hh*4..hh*4+3
    ull acc[4] = {0,0,0,0};
    const float* vb = g_val + bi*NTOK*DIMK;
    int rmax = nvalid - 1 + 2*WINW;
    for (int r=0; r<=rmax; r++){
        int cl = min(max(base+r,0), NTOK-1);
        ull v2 = *(const ull*)&vb[cl*DIMK + 2*d2];
        #pragma unroll
        for (int ii=0; ii<4; ii++){
            int jo = r - (hh*4+ii);
            if (jo>=0 && jo<KNB){
                ull wd = *(const ull*)&sSd[(hh*4+ii)*132 + jo];
                fma2(acc[ii], wd, v2);
            }
        }
    }

    // epilogue: updated = val + dval; conditional unit-norm (touched)
    float2 u[4];
    #pragma unroll
    for (int ii=0; ii<4; ii++){
        int i = hh*4+ii, n = t0+i;
        if (n < NTOK){
            ull vres = *(const ull*)&vb[n*DIMK + 2*d2];
            ull up = add2(vres, acc[ii]);
            u[ii] = upk(up);
            float2 a = upk(acc[ii]);
            float s2 = u[ii].x*u[ii].x + u[ii].y*u[ii].y;
            float am = fmaxf(fabsf(a.x), fabsf(a.y));
            #pragma unroll
            for (int o=16;o;o>>=1){ s2 += __shfl_xor_sync(~0u,s2,o); am = fmaxf(am, __shfl_xor_sync(~0u,am,o)); }
            if (lane==0){ atomicAdd(&sSum[i], s2); atomicMax(&sMax[i], __float_as_uint(am)); }
        }
    }
    __syncthreads();
    float* v2o = g_val2 + bi*NTOK*DIMK;
    #pragma unroll
    for (int ii=0; ii<4; ii++){
        int i = hh*4+ii, n = t0+i;
        if (n < NTOK){
            bool touched = __uint_as_float(sMax[i]) > 0.f;
            float inv = touched ? 1.f/fmaxf(sqrtf(sSum[i]), EPSV) : 1.f;
            *(float2*)&v2o[n*DIMK + 2*d2] = make_float2(u[ii].x*inv, u[ii].y*inv);
        }
    }
}

// ---------------- batch-global signed softmax over state ----------------------
__global__ void k_state_sm(float* __restrict__ out, int last){
    __shared__ float sred[32];
    int bi = blockIdx.x, tid = threadIdx.x, lane = tid&31, w = tid>>5;
    const float* in = g_state2 + bi*NTOK;
    float* dst = last ? out : g_state;
    int n0 = tid, n1 = tid+1024, n2 = tid+2048;
    float v0=0.f, v1=0.f, v2=0.f;
    float m = -INFINITY;
    if (n0<NTOK){ v0=in[n0]; m=fmaxf(m,fabsf(v0)); }
    if (n1<NTOK){ v1=in[n1]; m=fmaxf(m,fabsf(v1)); }
    if (n2<NTOK){ v2=in[n2]; m=fmaxf(m,fabsf(v2)); }
    #pragma unroll
    for (int o=16;o;o>>=1) m = fmaxf(m, __shfl_xor_sync(~0u,m,o));
    if (lane==0) sred[w] = m;
    __syncthreads();
    if (w==0){ float x = sred[lane];
        #pragma unroll
        for (int o=16;o;o>>=1) x = fmaxf(x, __shfl_xor_sync(~0u,x,o));
        if (lane==0) sred[0]=x; }
    __syncthreads();
    float mm = sred[0];
    __syncthreads();
    float e0=0.f, e1=0.f, e2=0.f, sum=0.f;
    if (n0<NTOK){ e0=expf(fabsf(v0)-mm); sum+=e0; }
    if (n1<NTOK){ e1=expf(fabsf(v1)-mm); sum+=e1; }
    if (n2<NTOK){ e2=expf(fabsf(v2)-mm); sum+=e2; }
    #pragma unroll
    for (int o=16;o;o>>=1) sum += __shfl_xor_sync(~0u,sum,o);
    if (lane==0) sred[w] = sum;
    __syncthreads();
    if (w==0){ float x = sred[lane];
        #pragma unroll
        for (int o=16;o;o>>=1) x += __shfl_xor_sync(~0u,x,o);
        if (lane==0) sred[0]=x; }
    __syncthreads();
    float inv = 1.f/sred[0];
    if (n0<NTOK) dst[bi*NTOK+n0] = sgnf(v0)*e0*inv;
    if (n1<NTOK) dst[bi*NTOK+n1] = sgnf(v1)*e1*inv;
    if (n2<NTOK) dst[bi*NTOK+n2] = sgnf(v2)*e2*inv;
}

// ---- MLP fc1 + gelu: 32-row tiles, 256-col halves, non-dup smem, f32x2 -------
__global__ void __launch_bounds__(256) k_mlp1(const float* __restrict__ W1,
                                              const float* __restrict__ b1, int layer){
    __shared__ __align__(16) float sA[32*DIMK];  // 32KB
    int row0 = blockIdx.x*32;
    int half = blockIdx.y;
    for (int e=threadIdx.x; e<32*DIMK; e+=256){
        int row = row0 + (e>>8);
        sA[e] = (row<ROWS) ? g_val2[row*DIMK + (e&255)] : 0.f;
    }
    __syncthreads();
    int cq = threadIdx.x & 63;    // 64 col quads -> 256 cols in this half
    int rg = threadIdx.x >> 6;    // rows rg*8..rg*8+7
    int col = half*256 + cq*4;
    const float* W = W1 + layer*DIMK*HID + col;
    ull acc[8][2] = {};
    for (int d=0; d<DIMK; d+=2){
        ulonglong2 w0 = *(const ulonglong2*)&W[(d+0)*HID];
        ulonglong2 w1 = *(const ulonglong2*)&W[(d+1)*HID];
        #pragma unroll
        for (int r=0;r<8;r++){
            float2 a = *(const float2*)&sA[(rg*8+r)*DIMK + d];
            ull ax = dup(a.x), ay = dup(a.y);
            fma2(acc[r][0], ax, w0.x); fma2(acc[r][1], ax, w0.y);
            fma2(acc[r][0], ay, w1.x); fma2(acc[r][1], ay, w1.y);
        }
    }
    float4 bv = *(const float4*)&b1[layer*HID + col];
    #pragma unroll
    for (int r=0;r<8;r++){
        int row = row0 + rg*8 + r;
        if (row<ROWS){
            float2 a0 = upk(acc[r][0]), a1 = upk(acc[r][1]);
            *(float4*)&g_h[row*HID + col] =
                make_float4(geluf(a0.x+bv.x), geluf(a0.y+bv.y), geluf(a1.x+bv.z), geluf(a1.y+bv.w));
        }
    }
}

// ---- MLP fc2 + residual + unit-norm: 24-row tiles, full 256 cols, f32x2 -------
#define M2ROWS 24
__global__ void __launch_bounds__(256) k_mlp2(const float* __restrict__ W2,
                                              const float* __restrict__ b2,
                                              int layer, float* __restrict__ out, int last){
    extern __shared__ __align__(16) float sH[];   // [24*512] = 48KB
    __shared__ float sSum[M2ROWS];
    int row0 = blockIdx.x*M2ROWS;
    for (int e=threadIdx.x; e<M2ROWS*HID; e+=256){
        int row = row0 + (e>>9);
        sH[e] = (row<ROWS) ? g_h[row*HID + (e&511)] : 0.f;
    }
    if (threadIdx.x<M2ROWS) sSum[threadIdx.x] = 0.f;
    __syncthreads();
    int cq = threadIdx.x & 63;    // 64 col quads -> 256 cols
    int rg = threadIdx.x >> 6;    // rows rg*6..rg*6+5
    int col = cq*4;
    const float* W = W2 + layer*HID*DIMK + col;
    ull acc[6][2] = {};
    for (int d=0; d<HID; d+=2){
        ulonglong2 w0 = *(const ulonglong2*)&W[(d+0)*DIMK];
        ulonglong2 w1 = *(const ulonglong2*)&W[(d+1)*DIMK];
        #pragma unroll
        for (int r=0;r<6;r++){
            float2 a = *(const float2*)&sH[(rg*6+r)*HID + d];
            ull ax = dup(a.x), ay = dup(a.y);
            fma2(acc[r][0], ax, w0.x); fma2(acc[r][1], ax, w0.y);
            fma2(acc[r][0], ay, w1.x); fma2(acc[r][1], ay, w1.y);
        }
    }
    float4 bv = *(const float4*)&b2[layer*DIMK + col];
    int lane = threadIdx.x & 31;
    float4 u[6];
    #pragma unroll
    for (int r=0;r<6;r++){
        int row = row0 + rg*6 + r;
        if (row<ROWS){
            float4 res = *(const float4*)&g_val2[row*DIMK + col];
            float2 a0 = upk(acc[r][0]), a1 = upk(acc[r][1]);
            u[r] = make_float4(res.x+a0.x+bv.x, res.y+a0.y+bv.y, res.z+a1.x+bv.z, res.w+a1.y+bv.w);
            float s2 = u[r].x*u[r].x + u[r].y*u[r].y + u[r].z*u[r].z + u[r].w*u[r].w;
            #pragma unroll
            for (int o=16;o;o>>=1) s2 += __shfl_xor_sync(~0u,s2,o);
            if (lane==0) atomicAdd(&sSum[rg*6+r], s2);
        }
    }
    __syncthreads();
    #pragma unroll
    for (int r=0;r<6;r++){
        int row = row0 + rg*6 + r;
        if (row<ROWS){
            float inv = 1.f/fmaxf(sqrtf(sSum[rg*6+r]), EPSV);
            if (last){
                // out+ROWS is only 8B-aligned (4098 floats) -> float2 stores
                float* dst = out + row*DIMK + col;
                *(float2*)&dst[0] = make_float2(u[r].x*inv, u[r].y*inv);
                *(float2*)&dst[2] = make_float2(u[r].z*inv, u[r].w*inv);
            } else {
                *(float4*)&g_val[row*DIMK + col] =
                    make_float4(u[r].x*inv, u[r].y*inv, u[r].z*inv, u[r].w*inv);
            }
        }
    }
}

extern "C" void kernel_launch(void* const* d_in, const int* in_sizes, int n_in,
                              void* d_out, int out_size){
    const int*   ids = (const int*)  d_in[0];
    const float* emb = (const float*)d_in[1];
    const float* pos = (const float*)d_in[2];
    const float* av  = (const float*)d_in[3];
    const float* as  = (const float*)d_in[4];
    const float* Ws  = (const float*)d_in[5];
    const float* bs  = (const float*)d_in[6];
    const float* U   = (const float*)d_in[7];
    const float* V   = (const float*)d_in[8];
    const float* W1  = (const float*)d_in[9];
    const float* b1  = (const float*)d_in[10];
    const float* W2  = (const float*)d_in[11];
    const float* b2  = (const float*)d_in[12];
    float* out = (float*)d_out;

    size_t attn_smem = ATTN_SMEM_FLOATS * sizeof(float);
    size_t mlp2_smem = M2ROWS*HID*sizeof(float);
    cudaFuncSetAttribute(k_attn, cudaFuncAttributeMaxDynamicSharedMemorySize, (int)attn_smem);
    cudaFuncSetAttribute(k_mlp2, cudaFuncAttributeMaxDynamicSharedMemorySize, (int)mlp2_smem);

    k_embed<<<ROWS, 256>>>(ids, emb, pos, av, as, Ws, bs);
    int rb16 = (ROWS + 15)/16;
    dim3 gm1((ROWS + 31)/32, 2);
    int gm2 = (ROWS + M2ROWS-1)/M2ROWS;
    dim3 ga((NTOK + 7)/8, BATCH);
    for (int l=0; l<NLAYERS; l++){
        int last = (l == NLAYERS-1);
        k_qk  <<<rb16, 256>>>(U, V, l);
        k_attn<<<ga, 256, attn_smem>>>();
        k_mlp1<<<gm1, 256>>>(W1, b1, l);            // 4th launch overall on l=0 -> ncu slot
        k_state_sm<<<BATCH, 1024>>>(out, last);
        k_mlp2<<<gm2, 256, mlp2_smem>>>(W2, b2, l, out + ROWS, last);
    }
}